// round 8
// baseline (speedup 1.0000x reference)
#include <cuda_runtime.h>
#include <cuda_bf16.h>
#include <cuda_fp8.h>
#include <cstdint>
#include <math.h>

#define DEV __device__ __forceinline__

// ---------------------------------------------------------------------------
// Problem constants
// ---------------------------------------------------------------------------
static constexpr int M_TOTAL = 16384;   // B*S
static constexpr int N_TOTAL = 2048;    // OUT
static constexpr int K_TOTAL = 2048;    // IN

static constexpr int BM = 128;
static constexpr int BN = 64;
static constexpr int BK = 64;                    // fp8 bytes per K-chunk
static constexpr int NUM_CHUNKS = K_TOTAL / BK;  // 32
static constexpr int STAGES = 4;
static constexpr int RS = 80;                    // padded row stride (64 + 16)
static constexpr int B_OFF = BM * RS;            // 10240
static constexpr int STAGE_BYTES = (BM + BN) * RS;      // 15360
static constexpr int SMEM_DYN = STAGES * STAGE_BYTES;   // 61440 -> 3 CTAs/SM (180KB)

// ---------------------------------------------------------------------------
// Scratch
// ---------------------------------------------------------------------------
__device__ uint8_t g_A[(size_t)M_TOTAL * K_TOTAL];   // 32 MB
__device__ uint8_t g_B[(size_t)N_TOTAL * K_TOTAL];   // 4 MB
__device__ int g_mode;   // qweight dtype: 0 = f32 codes, 1 = bf16 codes, 2 = raw bytes

// ---------------------------------------------------------------------------
// PTX helpers
// ---------------------------------------------------------------------------
DEV uint32_t smem_u32(const void* p) {
    uint32_t a;
    asm("{ .reg .u64 t; cvta.to.shared.u64 t, %1; cvt.u32.u64 %0, t; }" : "=r"(a) : "l"(p));
    return a;
}

#define LDSM_X4(r0, r1, r2, r3, addr) \
    asm volatile("ldmatrix.sync.aligned.m8n8.x4.shared.b16 {%0,%1,%2,%3}, [%4];" \
                 : "=r"(r0), "=r"(r1), "=r"(r2), "=r"(r3) : "r"(addr))

// fp8 e4m3 MMA (validated R5-R7)
#define MMA_E4M3(c, a0, a1, a2, a3, b0, b1) \
    asm volatile("mma.sync.aligned.m16n8k32.row.col.f32.e4m3.e4m3.f32 " \
                 "{%0,%1,%2,%3}, {%4,%5,%6,%7}, {%8,%9}, {%0,%1,%2,%3};" \
                 : "+f"((c)[0]), "+f"((c)[1]), "+f"((c)[2]), "+f"((c)[3]) \
                 : "r"(a0), "r"(a1), "r"(a2), "r"(a3), "r"(b0), "r"(b1))

#define CP_ASYNC_16(dst, src) \
    asm volatile("cp.async.cg.shared.global [%0], [%1], 16;" :: "r"(dst), "l"(src))

DEV bool e4m3_exact(float v) {
    if (!isfinite(v) || fabsf(v) > 448.0f) return false;
    __nv_fp8_e4m3 e(v);
    return (float)e == v;
}

// ---------------------------------------------------------------------------
// Kernel 0: probe qweight dtype (f32 tested before bf16)
// ---------------------------------------------------------------------------
__global__ void fp8lin_detect(const void* qw) {
    __shared__ int ok32s, okbfs;
    const int t = threadIdx.x;
    if (t == 0) { ok32s = 1; okbfs = 1; }
    __syncthreads();

    const float* f = (const float*)qw;
    const unsigned short* hb = (const unsigned short*)qw;
    bool ok32 = true, okbf = true;
#pragma unroll
    for (int j = 0; j < 4; j++)
        if (!e4m3_exact(f[t * 4 + j])) ok32 = false;
#pragma unroll
    for (int j = 0; j < 8; j++)
        if (!e4m3_exact(__bfloat162float(__ushort_as_bfloat16(hb[t * 8 + j])))) okbf = false;

    if (!ok32) ok32s = 0;
    if (!okbf) okbfs = 0;
    __syncthreads();
    if (t == 0) g_mode = ok32s ? 0 : (okbfs ? 1 : 2);
}

// ---------------------------------------------------------------------------
// Kernel 1: x -> e4m3 bytes, 16 elems/thread
// ---------------------------------------------------------------------------
__global__ void __launch_bounds__(256) fp8lin_quant(const float* __restrict__ x,
                                                    const float* __restrict__ in_scale) {
    const float r = 1.0f / __ldg(in_scale);
    const size_t i = ((size_t)blockIdx.x * blockDim.x + threadIdx.x) * 16;
    const float4* src = reinterpret_cast<const float4*>(x + i);

    unsigned short h[8];
#pragma unroll
    for (int j = 0; j < 4; j++) {
        float4 v = src[j];
        float2 p0 = make_float2(v.x * r, v.y * r);
        float2 p1 = make_float2(v.z * r, v.w * r);
        h[2 * j + 0] = (unsigned short)__nv_cvt_float2_to_fp8x2(p0, __NV_SATFINITE, __NV_E4M3);
        h[2 * j + 1] = (unsigned short)__nv_cvt_float2_to_fp8x2(p1, __NV_SATFINITE, __NV_E4M3);
    }
    uint4 o;
    o.x = (uint32_t)h[0] | ((uint32_t)h[1] << 16);
    o.y = (uint32_t)h[2] | ((uint32_t)h[3] << 16);
    o.z = (uint32_t)h[4] | ((uint32_t)h[5] << 16);
    o.w = (uint32_t)h[6] | ((uint32_t)h[7] << 16);
    *reinterpret_cast<uint4*>(&g_A[i]) = o;
}

// ---------------------------------------------------------------------------
// Kernel 2: qweight -> e4m3 bytes (3 dtype modes)
// ---------------------------------------------------------------------------
__global__ void __launch_bounds__(256) fp8lin_wconv(const void* __restrict__ qw) {
    const int mode = g_mode;
    const size_t i = ((size_t)blockIdx.x * blockDim.x + threadIdx.x) * 16;

    uint4 o;
    if (mode == 0) {                       // float32 code values (expected)
        const float4* s = reinterpret_cast<const float4*>((const float*)qw + i);
        unsigned short h[8];
#pragma unroll
        for (int j = 0; j < 4; j++) {
            float4 v = s[j];
            float2 p0 = make_float2(v.x, v.y);
            float2 p1 = make_float2(v.z, v.w);
            h[2 * j + 0] = (unsigned short)__nv_cvt_float2_to_fp8x2(p0, __NV_SATFINITE, __NV_E4M3);
            h[2 * j + 1] = (unsigned short)__nv_cvt_float2_to_fp8x2(p1, __NV_SATFINITE, __NV_E4M3);
        }
        o.x = (uint32_t)h[0] | ((uint32_t)h[1] << 16);
        o.y = (uint32_t)h[2] | ((uint32_t)h[3] << 16);
        o.z = (uint32_t)h[4] | ((uint32_t)h[5] << 16);
        o.w = (uint32_t)h[6] | ((uint32_t)h[7] << 16);
    } else if (mode == 2) {                // raw e4m3 bytes
        o = *reinterpret_cast<const uint4*>((const uint8_t*)qw + i);
    } else {                               // bf16 codes
        const unsigned short* s = (const unsigned short*)qw + i;
        unsigned short h[8];
#pragma unroll
        for (int j = 0; j < 8; j++) {
            float2 p = make_float2(__bfloat162float(__ushort_as_bfloat16(s[2 * j])),
                                   __bfloat162float(__ushort_as_bfloat16(s[2 * j + 1])));
            h[j] = (unsigned short)__nv_cvt_float2_to_fp8x2(p, __NV_SATFINITE, __NV_E4M3);
        }
        o.x = (uint32_t)h[0] | ((uint32_t)h[1] << 16);
        o.y = (uint32_t)h[2] | ((uint32_t)h[3] << 16);
        o.z = (uint32_t)h[4] | ((uint32_t)h[5] << 16);
        o.w = (uint32_t)h[6] | ((uint32_t)h[7] << 16);
    }
    *reinterpret_cast<uint4*>(&g_B[i]) = o;
}

// ---------------------------------------------------------------------------
// Kernel 3: fp8 QMMA GEMM — 128x64 CTA tile, 3 CTAs/SM, 4-stage pipeline
// ---------------------------------------------------------------------------
__global__ void __launch_bounds__(256, 3) fp8lin_gemm(float* __restrict__ out,
                                                      const float* __restrict__ in_scale,
                                                      const float* __restrict__ w_scale,
                                                      const float* __restrict__ bias) {
    extern __shared__ char dsm[];
    const uint32_t smem0 = smem_u32(dsm);

    const int tid = threadIdx.x;
    const int wid = tid >> 5;
    const int lane = tid & 31;
    const int warp_m = wid >> 2;        // 0..1 -> 64 rows
    const int warp_n = wid & 3;         // 0..3 -> 16 cols

    const int n0 = blockIdx.x * BN;     // N fastest -> A-tile L2 reuse (32 CTAs)
    const int m0 = blockIdx.y * BM;

    // ---- loader: 768 x 16B segments (A 512, B 256) = 3 per thread ----
    const int lrow = tid >> 2;          // 0..63
    const int lseg = (tid & 3) * 16;
    const uint8_t* sA0 = g_A + (size_t)(m0 + lrow) * K_TOTAL + lseg;
    const uint8_t* sA1 = sA0 + (size_t)64 * K_TOTAL;
    const uint8_t* sB0 = g_B + (size_t)(n0 + lrow) * K_TOTAL + lseg;
    const uint32_t dA0 = (uint32_t)(lrow * RS + lseg);
    const uint32_t dA1 = dA0 + 64 * RS;
    const uint32_t dB0 = dA0 + B_OFF;

#define ISSUE_STAGE(stage_base) do { \
        CP_ASYNC_16((stage_base) + dA0, sA0); \
        CP_ASYNC_16((stage_base) + dA1, sA1); \
        CP_ASYNC_16((stage_base) + dB0, sB0); \
        sA0 += BK; sA1 += BK; sB0 += BK; \
        asm volatile("cp.async.commit_group;"); \
    } while (0)

    // ---- ldmatrix bases ----
    // A x4: mat = lane>>3; row = (mat&1)*8 + (lane&7); k-byte = (mat>>1)*16
    const int amat = lane >> 3;
    const uint32_t a_base = smem0
        + (uint32_t)((warp_m * 64 + (amat & 1) * 8 + (lane & 7)) * RS + (amat >> 1) * 16);
    // B x4 (both nt tiles of the 16-col slab): row = warp_n*16 + (lane>>4)*8 + (lane&7),
    // k-half = (lane>>3)&1  ->  r0,r1 = nt0 (k0,k16); r2,r3 = nt1
    const uint32_t b_base = smem0 + (uint32_t)(B_OFF
        + (warp_n * 16 + ((lane >> 4) * 8) + (lane & 7)) * RS + ((lane >> 3) & 1) * 16);

    float acc[4][2][4];
#pragma unroll
    for (int mt = 0; mt < 4; mt++)
#pragma unroll
        for (int nt = 0; nt < 2; nt++)
#pragma unroll
            for (int q = 0; q < 4; q++) acc[mt][nt][q] = 0.0f;

#define COMPUTE_CHUNK(soff) do { \
        _Pragma("unroll") \
        for (int ks = 0; ks < 2; ks++) { \
            uint32_t a[4][4], b[2][2]; \
            LDSM_X4(b[0][0], b[0][1], b[1][0], b[1][1], \
                    b_base + (soff) + (uint32_t)(ks * 32)); \
            _Pragma("unroll") \
            for (int mt = 0; mt < 4; mt++) \
                LDSM_X4(a[mt][0], a[mt][1], a[mt][2], a[mt][3], \
                        a_base + (soff) + (uint32_t)(mt * 16 * RS + ks * 32)); \
            _Pragma("unroll") \
            for (int mt = 0; mt < 4; mt++) { \
                MMA_E4M3(acc[mt][0], a[mt][0], a[mt][1], a[mt][2], a[mt][3], \
                         b[0][0], b[0][1]); \
                MMA_E4M3(acc[mt][1], a[mt][0], a[mt][1], a[mt][2], a[mt][3], \
                         b[1][0], b[1][1]); \
            } \
        } \
    } while (0)

    // Prefill stages 0..2 with chunks 0..2
    ISSUE_STAGE(smem0 + 0 * STAGE_BYTES);
    ISSUE_STAGE(smem0 + 1 * STAGE_BYTES);
    ISSUE_STAGE(smem0 + 2 * STAGE_BYTES);

    // Main: c = 0..27 (issue c+3 <= 30); peeled tail below
#pragma unroll 4
    for (int c = 0; c < NUM_CHUNKS - 4; c++) {
        asm volatile("cp.async.wait_group 2;");
        __syncthreads();
        ISSUE_STAGE(smem0 + (uint32_t)(((c + 3) & 3) * STAGE_BYTES));
        COMPUTE_CHUNK((uint32_t)((c & 3) * STAGE_BYTES));
    }
    {   // c = 28: issue chunk 31
        asm volatile("cp.async.wait_group 2;");
        __syncthreads();
        ISSUE_STAGE(smem0 + (uint32_t)(3 * STAGE_BYTES));
        COMPUTE_CHUNK((uint32_t)(0 * STAGE_BYTES));
    }
    {   // c = 29
        asm volatile("cp.async.wait_group 2;");
        __syncthreads();
        COMPUTE_CHUNK((uint32_t)(1 * STAGE_BYTES));
    }
    {   // c = 30
        asm volatile("cp.async.wait_group 1;");
        __syncthreads();
        COMPUTE_CHUNK((uint32_t)(2 * STAGE_BYTES));
    }
    {   // c = 31
        asm volatile("cp.async.wait_group 0;");
        __syncthreads();
        COMPUTE_CHUNK((uint32_t)(3 * STAGE_BYTES));
    }
#undef ISSUE_STAGE
#undef COMPUTE_CHUNK

    // ---------------- Epilogue: dequant scale + bias ----------------
    const float sc = __ldg(in_scale) * __ldg(w_scale);
    const int gid = lane >> 2;
    const int tig = lane & 3;

    float2 bv[2];
#pragma unroll
    for (int nt = 0; nt < 2; nt++)
        bv[nt] = *reinterpret_cast<const float2*>(bias + n0 + warp_n * 16 + nt * 8 + 2 * tig);

#pragma unroll
    for (int mt = 0; mt < 4; mt++) {
        const int row = m0 + warp_m * 64 + mt * 16 + gid;
#pragma unroll
        for (int nt = 0; nt < 2; nt++) {
            const int col = n0 + warp_n * 16 + nt * 8 + 2 * tig;
            float2 o0, o1;
            o0.x = acc[mt][nt][0] * sc + bv[nt].x;
            o0.y = acc[mt][nt][1] * sc + bv[nt].y;
            o1.x = acc[mt][nt][2] * sc + bv[nt].x;
            o1.y = acc[mt][nt][3] * sc + bv[nt].y;
            *reinterpret_cast<float2*>(out + (size_t)row * N_TOTAL + col) = o0;
            *reinterpret_cast<float2*>(out + (size_t)(row + 8) * N_TOTAL + col) = o1;
        }
    }
}

// ---------------------------------------------------------------------------
// Launch
// ---------------------------------------------------------------------------
extern "C" void kernel_launch(void* const* d_in, const int* in_sizes, int n_in,
                              void* d_out, int out_size) {
    const float* x = nullptr;
    const void* qweight = nullptr;
    const float* bias = nullptr;
    const float* s_first = nullptr;
    const float* s_second = nullptr;
    int x_idx = -1;

    for (int i = 0; i < n_in; i++) {
        long long sz = in_sizes[i];
        if (sz == (long long)M_TOTAL * K_TOTAL) { x = (const float*)d_in[i]; x_idx = i; }
        else if (sz == (long long)N_TOTAL * K_TOTAL) qweight = d_in[i];
        else if (sz == N_TOTAL) bias = (const float*)d_in[i];
        else if (sz == 1) { if (!s_first) s_first = (const float*)d_in[i];
                            else s_second = (const float*)d_in[i]; }
    }
    const float* wscale = (x_idx == 0) ? s_first : s_second;
    const float* iscale = (x_idx == 0) ? s_second : s_first;
    float* out = (float*)d_out;

    fp8lin_detect<<<1, 256>>>(qweight);
    const size_t total = (size_t)M_TOTAL * K_TOTAL;
    fp8lin_quant<<<(unsigned)(total / (16 * 256)), 256>>>(x, iscale);
    fp8lin_wconv<<<(unsigned)((size_t)N_TOTAL * K_TOTAL / (16 * 256)), 256>>>(qweight);

    cudaFuncSetAttribute(fp8lin_gemm, cudaFuncAttributeMaxDynamicSharedMemorySize, SMEM_DYN);
    dim3 grid(N_TOTAL / BN, M_TOTAL / BM);
    fp8lin_gemm<<<grid, 256, SMEM_DYN>>>(out, iscale, wscale, bias);
}

// round 9
// speedup vs baseline: 1.1348x; 1.1348x over previous
#include <cuda_runtime.h>
#include <cuda_bf16.h>
#include <cuda_fp8.h>
#include <cstdint>
#include <math.h>

#define DEV __device__ __forceinline__

// ---------------------------------------------------------------------------
// Problem constants
// ---------------------------------------------------------------------------
static constexpr int M_TOTAL = 16384;   // B*S
static constexpr int N_TOTAL = 2048;    // OUT
static constexpr int K_TOTAL = 2048;    // IN

static constexpr int BM = 128;
static constexpr int BN = 128;
static constexpr int BK = 128;                   // fp8 bytes per K-chunk (full row)
static constexpr int NUM_CHUNKS = K_TOTAL / BK;  // 16
static constexpr int STAGES = 3;
static constexpr int RS = 144;                   // padded row stride (128 + 16)
static constexpr int B_OFF = BM * RS;            // 18432
static constexpr int STAGE_BYTES = (BM + BN) * RS;      // 36864
static constexpr int SMEM_DYN = STAGES * STAGE_BYTES;   // 110592 -> 2 CTAs/SM

// ---------------------------------------------------------------------------
// Scratch
// ---------------------------------------------------------------------------
__device__ uint8_t g_A[(size_t)M_TOTAL * K_TOTAL];   // 32 MB
__device__ uint8_t g_B[(size_t)N_TOTAL * K_TOTAL];   // 4 MB

// ---------------------------------------------------------------------------
// PTX helpers
// ---------------------------------------------------------------------------
DEV uint32_t smem_u32(const void* p) {
    uint32_t a;
    asm("{ .reg .u64 t; cvta.to.shared.u64 t, %1; cvt.u32.u64 %0, t; }" : "=r"(a) : "l"(p));
    return a;
}

#define LDSM_X4(r0, r1, r2, r3, addr) \
    asm volatile("ldmatrix.sync.aligned.m8n8.x4.shared.b16 {%0,%1,%2,%3}, [%4];" \
                 : "=r"(r0), "=r"(r1), "=r"(r2), "=r"(r3) : "r"(addr))

// fp8 e4m3 MMA (validated R5-R8)
#define MMA_E4M3(c, a0, a1, a2, a3, b0, b1) \
    asm volatile("mma.sync.aligned.m16n8k32.row.col.f32.e4m3.e4m3.f32 " \
                 "{%0,%1,%2,%3}, {%4,%5,%6,%7}, {%8,%9}, {%0,%1,%2,%3};" \
                 : "+f"((c)[0]), "+f"((c)[1]), "+f"((c)[2]), "+f"((c)[3]) \
                 : "r"(a0), "r"(a1), "r"(a2), "r"(a3), "r"(b0), "r"(b1))

#define CP_ASYNC_16(dst, src) \
    asm volatile("cp.async.cg.shared.global [%0], [%1], 16;" :: "r"(dst), "l"(src))

DEV bool e4m3_exact(float v) {
    if (!isfinite(v) || fabsf(v) > 448.0f) return false;
    __nv_fp8_e4m3 e(v);
    return (float)e == v;
}

// ---------------------------------------------------------------------------
// Kernel 1: x -> e4m3 bytes, 16 elems/thread
// ---------------------------------------------------------------------------
__global__ void __launch_bounds__(256) fp8lin_quant(const float* __restrict__ x,
                                                    const float* __restrict__ in_scale) {
    const float r = 1.0f / __ldg(in_scale);
    const size_t i = ((size_t)blockIdx.x * blockDim.x + threadIdx.x) * 16;
    const float4* src = reinterpret_cast<const float4*>(x + i);

    unsigned short h[8];
#pragma unroll
    for (int j = 0; j < 4; j++) {
        float4 v = src[j];
        float2 p0 = make_float2(v.x * r, v.y * r);
        float2 p1 = make_float2(v.z * r, v.w * r);
        h[2 * j + 0] = (unsigned short)__nv_cvt_float2_to_fp8x2(p0, __NV_SATFINITE, __NV_E4M3);
        h[2 * j + 1] = (unsigned short)__nv_cvt_float2_to_fp8x2(p1, __NV_SATFINITE, __NV_E4M3);
    }
    uint4 o;
    o.x = (uint32_t)h[0] | ((uint32_t)h[1] << 16);
    o.y = (uint32_t)h[2] | ((uint32_t)h[3] << 16);
    o.z = (uint32_t)h[4] | ((uint32_t)h[5] << 16);
    o.w = (uint32_t)h[6] | ((uint32_t)h[7] << 16);
    *reinterpret_cast<uint4*>(&g_A[i]) = o;
}

// ---------------------------------------------------------------------------
// Kernel 2: qweight -> e4m3 bytes, with per-block dtype probe (no extra kernel)
// Every block probes the same leading 256 floats (1 KB, L2-resident).
// f32 must be tested before bf16 (valid f32 codes also pass the bf16 test).
// ---------------------------------------------------------------------------
__global__ void __launch_bounds__(256) fp8lin_wconv(const void* __restrict__ qw) {
    __shared__ int ok32s, okbfs;
    const int t = threadIdx.x;
    if (t == 0) { ok32s = 1; okbfs = 1; }
    __syncthreads();
    {
        const float* f = (const float*)qw;
        const unsigned short* hb = (const unsigned short*)qw;
        if (!e4m3_exact(f[t])) ok32s = 0;    // benign race: writers all store 0
        bool okbf = e4m3_exact(__bfloat162float(__ushort_as_bfloat16(hb[2 * t]))) &&
                    e4m3_exact(__bfloat162float(__ushort_as_bfloat16(hb[2 * t + 1])));
        if (!okbf) okbfs = 0;
    }
    __syncthreads();
    const int mode = ok32s ? 0 : (okbfs ? 1 : 2);

    const size_t i = ((size_t)blockIdx.x * blockDim.x + threadIdx.x) * 16;
    uint4 o;
    if (mode == 0) {                       // float32 code values (expected)
        const float4* s = reinterpret_cast<const float4*>((const float*)qw + i);
        unsigned short h[8];
#pragma unroll
        for (int j = 0; j < 4; j++) {
            float4 v = s[j];
            float2 p0 = make_float2(v.x, v.y);
            float2 p1 = make_float2(v.z, v.w);
            h[2 * j + 0] = (unsigned short)__nv_cvt_float2_to_fp8x2(p0, __NV_SATFINITE, __NV_E4M3);
            h[2 * j + 1] = (unsigned short)__nv_cvt_float2_to_fp8x2(p1, __NV_SATFINITE, __NV_E4M3);
        }
        o.x = (uint32_t)h[0] | ((uint32_t)h[1] << 16);
        o.y = (uint32_t)h[2] | ((uint32_t)h[3] << 16);
        o.z = (uint32_t)h[4] | ((uint32_t)h[5] << 16);
        o.w = (uint32_t)h[6] | ((uint32_t)h[7] << 16);
    } else if (mode == 2) {                // raw e4m3 bytes
        o = *reinterpret_cast<const uint4*>((const uint8_t*)qw + i);
    } else {                               // bf16 codes
        const unsigned short* s = (const unsigned short*)qw + i;
        unsigned short h[8];
#pragma unroll
        for (int j = 0; j < 8; j++) {
            float2 p = make_float2(__bfloat162float(__ushort_as_bfloat16(s[2 * j])),
                                   __bfloat162float(__ushort_as_bfloat16(s[2 * j + 1])));
            h[j] = (unsigned short)__nv_cvt_float2_to_fp8x2(p, __NV_SATFINITE, __NV_E4M3);
        }
        o.x = (uint32_t)h[0] | ((uint32_t)h[1] << 16);
        o.y = (uint32_t)h[2] | ((uint32_t)h[3] << 16);
        o.z = (uint32_t)h[4] | ((uint32_t)h[5] << 16);
        o.w = (uint32_t)h[6] | ((uint32_t)h[7] << 16);
    }
    *reinterpret_cast<uint4*>(&g_B[i]) = o;
}

// ---------------------------------------------------------------------------
// Kernel 3: fp8 QMMA GEMM — BK=128, 3 stages, 2 CTAs/SM, ks-pipelined frags
// ---------------------------------------------------------------------------
__global__ void __launch_bounds__(256, 2) fp8lin_gemm(float* __restrict__ out,
                                                      const float* __restrict__ in_scale,
                                                      const float* __restrict__ w_scale,
                                                      const float* __restrict__ bias) {
    extern __shared__ char dsm[];
    const uint32_t smem0 = smem_u32(dsm);

    const int tid = threadIdx.x;
    const int wid = tid >> 5;
    const int lane = tid & 31;
    const int warp_m = wid >> 2;        // 0..1 -> 64 rows
    const int warp_n = wid & 3;         // 0..3 -> 32 cols

    const int n0 = blockIdx.x * BN;     // N fastest -> A-tile L2 reuse
    const int m0 = blockIdx.y * BM;

    // ---- loader: 8 src pointers, 8 dst offsets (cold during compute) ----
    const int brow = tid >> 3;          // 0..31
    const int seg = (tid & 7) * 16;     // 0..112
    const uint8_t* sA[4];
    const uint8_t* sB[4];
    uint32_t dA[4], dB[4];
#pragma unroll
    for (int i = 0; i < 4; i++) {
        sA[i] = g_A + (size_t)(m0 + brow + 32 * i) * K_TOTAL + seg;
        sB[i] = g_B + (size_t)(n0 + brow + 32 * i) * K_TOTAL + seg;
        dA[i] = (uint32_t)((brow + 32 * i) * RS + seg);
        dB[i] = (uint32_t)(B_OFF + (brow + 32 * i) * RS + seg);
    }

#define ISSUE_STAGE(stage_base) do { \
        CP_ASYNC_16((stage_base) + dA[0], sA[0]); \
        CP_ASYNC_16((stage_base) + dA[1], sA[1]); \
        CP_ASYNC_16((stage_base) + dA[2], sA[2]); \
        CP_ASYNC_16((stage_base) + dA[3], sA[3]); \
        CP_ASYNC_16((stage_base) + dB[0], sB[0]); \
        CP_ASYNC_16((stage_base) + dB[1], sB[1]); \
        CP_ASYNC_16((stage_base) + dB[2], sB[2]); \
        CP_ASYNC_16((stage_base) + dB[3], sB[3]); \
        sA[0] += BK; sA[1] += BK; sA[2] += BK; sA[3] += BK; \
        sB[0] += BK; sB[1] += BK; sB[2] += BK; sB[3] += BK; \
        asm volatile("cp.async.commit_group;"); \
    } while (0)

    // ---- ldmatrix bases (validated R6/R7) ----
    const int amat = lane >> 3;
    const uint32_t a_base = smem0
        + (uint32_t)((warp_m * 64 + (amat & 1) * 8 + (lane & 7)) * RS + (amat >> 1) * 16);
    const uint32_t b_base = smem0 + (uint32_t)(B_OFF
        + (warp_n * 32 + ((lane >> 4) * 8) + (lane & 7)) * RS + ((lane >> 3) & 1) * 16);

    float acc[4][4][4];
#pragma unroll
    for (int mt = 0; mt < 4; mt++)
#pragma unroll
        for (int nt = 0; nt < 4; nt++)
#pragma unroll
            for (int q = 0; q < 4; q++) acc[mt][nt][q] = 0.0f;

    // Fragment double buffers (ks-level software pipeline)
    uint32_t af[2][4][4], bf[2][4][2];

#define LOAD_FRAGS(p, soff, ks) do { \
        _Pragma("unroll") \
        for (int mt = 0; mt < 4; mt++) \
            LDSM_X4(af[p][mt][0], af[p][mt][1], af[p][mt][2], af[p][mt][3], \
                    a_base + (soff) + (uint32_t)(mt * 16 * RS + (ks) * 32)); \
        LDSM_X4(bf[p][0][0], bf[p][0][1], bf[p][1][0], bf[p][1][1], \
                b_base + (soff) + (uint32_t)((ks) * 32)); \
        LDSM_X4(bf[p][2][0], bf[p][2][1], bf[p][3][0], bf[p][3][1], \
                b_base + (soff) + (uint32_t)(16 * RS + (ks) * 32)); \
    } while (0)

#define MMA_SET(p) do { \
        _Pragma("unroll") \
        for (int mt = 0; mt < 4; mt++) \
            _Pragma("unroll") \
            for (int nt = 0; nt < 4; nt++) \
                MMA_E4M3(acc[mt][nt], af[p][mt][0], af[p][mt][1], af[p][mt][2], \
                         af[p][mt][3], bf[p][nt][0], bf[p][nt][1]); \
    } while (0)

#define COMPUTE_CHUNK(soff) do { \
        LOAD_FRAGS(0, (soff), 0); \
        LOAD_FRAGS(1, (soff), 1);  MMA_SET(0); \
        LOAD_FRAGS(0, (soff), 2);  MMA_SET(1); \
        LOAD_FRAGS(1, (soff), 3);  MMA_SET(0); \
        MMA_SET(1); \
    } while (0)

    // Prefill stages 0,1 with chunks 0,1
    ISSUE_STAGE(smem0 + 0 * STAGE_BYTES);
    ISSUE_STAGE(smem0 + 1 * STAGE_BYTES);

#pragma unroll
    for (int c = 0; c < NUM_CHUNKS; c++) {
        if (c < NUM_CHUNKS - 1)
            asm volatile("cp.async.wait_group 1;");
        else
            asm volatile("cp.async.wait_group 0;");
        __syncthreads();

        if (c + 2 < NUM_CHUNKS)
            ISSUE_STAGE(smem0 + (uint32_t)(((c + 2) % STAGES) * STAGE_BYTES));

        COMPUTE_CHUNK((uint32_t)((c % STAGES) * STAGE_BYTES));
    }
#undef ISSUE_STAGE
#undef LOAD_FRAGS
#undef MMA_SET
#undef COMPUTE_CHUNK

    // ---------------- Epilogue: dequant scale + bias ----------------
    const float sc = __ldg(in_scale) * __ldg(w_scale);
    const int gid = lane >> 2;
    const int tig = lane & 3;

    float2 bv[4];
#pragma unroll
    for (int nt = 0; nt < 4; nt++)
        bv[nt] = *reinterpret_cast<const float2*>(bias + n0 + warp_n * 32 + nt * 8 + 2 * tig);

#pragma unroll
    for (int mt = 0; mt < 4; mt++) {
        const int row = m0 + warp_m * 64 + mt * 16 + gid;
#pragma unroll
        for (int nt = 0; nt < 4; nt++) {
            const int col = n0 + warp_n * 32 + nt * 8 + 2 * tig;
            float2 o0, o1;
            o0.x = acc[mt][nt][0] * sc + bv[nt].x;
            o0.y = acc[mt][nt][1] * sc + bv[nt].y;
            o1.x = acc[mt][nt][2] * sc + bv[nt].x;
            o1.y = acc[mt][nt][3] * sc + bv[nt].y;
            *reinterpret_cast<float2*>(out + (size_t)row * N_TOTAL + col) = o0;
            *reinterpret_cast<float2*>(out + (size_t)(row + 8) * N_TOTAL + col) = o1;
        }
    }
}

// ---------------------------------------------------------------------------
// Launch
// ---------------------------------------------------------------------------
extern "C" void kernel_launch(void* const* d_in, const int* in_sizes, int n_in,
                              void* d_out, int out_size) {
    const float* x = nullptr;
    const void* qweight = nullptr;
    const float* bias = nullptr;
    const float* s_first = nullptr;
    const float* s_second = nullptr;
    int x_idx = -1;

    for (int i = 0; i < n_in; i++) {
        long long sz = in_sizes[i];
        if (sz == (long long)M_TOTAL * K_TOTAL) { x = (const float*)d_in[i]; x_idx = i; }
        else if (sz == (long long)N_TOTAL * K_TOTAL) qweight = d_in[i];
        else if (sz == N_TOTAL) bias = (const float*)d_in[i];
        else if (sz == 1) { if (!s_first) s_first = (const float*)d_in[i];
                            else s_second = (const float*)d_in[i]; }
    }
    const float* wscale = (x_idx == 0) ? s_first : s_second;
    const float* iscale = (x_idx == 0) ? s_second : s_first;
    float* out = (float*)d_out;

    const size_t total = (size_t)M_TOTAL * K_TOTAL;
    fp8lin_quant<<<(unsigned)(total / (16 * 256)), 256>>>(x, iscale);
    fp8lin_wconv<<<(unsigned)((size_t)N_TOTAL * K_TOTAL / (16 * 256)), 256>>>(qweight);

    cudaFuncSetAttribute(fp8lin_gemm, cudaFuncAttributeMaxDynamicSharedMemorySize, SMEM_DYN);
    dim3 grid(N_TOTAL / BN, M_TOTAL / BM);
    fp8lin_gemm<<<grid, 256, SMEM_DYN>>>(out, iscale, wscale, bias);
}

// round 11
// speedup vs baseline: 1.6671x; 1.4690x over previous
#include <cuda_runtime.h>
#include <cuda_bf16.h>
#include <cuda_fp8.h>
#include <cstdint>
#include <math.h>

#define DEV __device__ __forceinline__

// ---------------------------------------------------------------------------
// Problem constants
// ---------------------------------------------------------------------------
static constexpr int M_TOTAL = 16384;   // B*S
static constexpr int N_TOTAL = 2048;    // OUT
static constexpr int K_TOTAL = 2048;    // IN

static constexpr int BM = 128;
static constexpr int BN = 128;
static constexpr int BK = 128;                   // fp8 bytes per K-chunk (full row)
static constexpr int NUM_CHUNKS = K_TOTAL / BK;  // 16
static constexpr int STAGES = 3;
static constexpr int RS = 144;                   // padded row stride (128 + 16)
static constexpr int B_OFF = BM * RS;            // 18432
static constexpr int STAGE_BYTES = (BM + BN) * RS;      // 36864
static constexpr int SMEM_DYN = STAGES * STAGE_BYTES;   // 110592 -> 2 CTAs/SM

// ---------------------------------------------------------------------------
// Scratch
// ---------------------------------------------------------------------------
__device__ uint8_t g_A[(size_t)M_TOTAL * K_TOTAL];   // 32 MB
__device__ uint8_t g_B[(size_t)N_TOTAL * K_TOTAL];   // 4 MB

// ---------------------------------------------------------------------------
// PTX helpers
// ---------------------------------------------------------------------------
DEV uint32_t smem_u32(const void* p) {
    uint32_t a;
    asm("{ .reg .u64 t; cvta.to.shared.u64 t, %1; cvt.u32.u64 %0, t; }" : "=r"(a) : "l"(p));
    return a;
}

#define LDSM_X4(r0, r1, r2, r3, addr) \
    asm volatile("ldmatrix.sync.aligned.m8n8.x4.shared.b16 {%0,%1,%2,%3}, [%4];" \
                 : "=r"(r0), "=r"(r1), "=r"(r2), "=r"(r3) : "r"(addr))

// fp8 e4m3 MMA (validated R5-R9)
#define MMA_E4M3(c, a0, a1, a2, a3, b0, b1) \
    asm volatile("mma.sync.aligned.m16n8k32.row.col.f32.e4m3.e4m3.f32 " \
                 "{%0,%1,%2,%3}, {%4,%5,%6,%7}, {%8,%9}, {%0,%1,%2,%3};" \
                 : "+f"((c)[0]), "+f"((c)[1]), "+f"((c)[2]), "+f"((c)[3]) \
                 : "r"(a0), "r"(a1), "r"(a2), "r"(a3), "r"(b0), "r"(b1))

#define CP_ASYNC_16(dst, src) \
    asm volatile("cp.async.cg.shared.global [%0], [%1], 16;" :: "r"(dst), "l"(src))

DEV bool e4m3_exact(float v) {
    if (!isfinite(v) || fabsf(v) > 448.0f) return false;
    __nv_fp8_e4m3 e(v);
    return (float)e == v;
}

// ---------------------------------------------------------------------------
// Kernel 1: x -> e4m3 bytes, 16 elems/thread (measured: 25us, 75% DRAM)
// ---------------------------------------------------------------------------
__global__ void __launch_bounds__(256) fp8lin_quant(const float* __restrict__ x,
                                                    const float* __restrict__ in_scale) {
    const float r = 1.0f / __ldg(in_scale);
    const size_t i = ((size_t)blockIdx.x * blockDim.x + threadIdx.x) * 16;
    const float4* src = reinterpret_cast<const float4*>(x + i);

    unsigned short h[8];
#pragma unroll
    for (int j = 0; j < 4; j++) {
        float4 v = src[j];
        float2 p0 = make_float2(v.x * r, v.y * r);
        float2 p1 = make_float2(v.z * r, v.w * r);
        h[2 * j + 0] = (unsigned short)__nv_cvt_float2_to_fp8x2(p0, __NV_SATFINITE, __NV_E4M3);
        h[2 * j + 1] = (unsigned short)__nv_cvt_float2_to_fp8x2(p1, __NV_SATFINITE, __NV_E4M3);
    }
    uint4 o;
    o.x = (uint32_t)h[0] | ((uint32_t)h[1] << 16);
    o.y = (uint32_t)h[2] | ((uint32_t)h[3] << 16);
    o.z = (uint32_t)h[4] | ((uint32_t)h[5] << 16);
    o.w = (uint32_t)h[6] | ((uint32_t)h[7] << 16);
    *reinterpret_cast<uint4*>(&g_A[i]) = o;
}

// ---------------------------------------------------------------------------
// Kernel 2: qweight -> e4m3 bytes, per-block dtype probe folded in (R9-validated)
// Every block probes the leading 256 floats (1 KB, L2-resident after block 0).
// f32 must be tested before bf16 (valid f32 codes also pass the bf16 test).
// ---------------------------------------------------------------------------
__global__ void __launch_bounds__(256) fp8lin_wconv(const void* __restrict__ qw) {
    __shared__ int ok32s, okbfs;
    const int t = threadIdx.x;
    if (t == 0) { ok32s = 1; okbfs = 1; }
    __syncthreads();
    {
        const float* f = (const float*)qw;
        const unsigned short* hb = (const unsigned short*)qw;
        if (!e4m3_exact(f[t])) ok32s = 0;    // benign race: writers all store 0
        bool okbf = e4m3_exact(__bfloat162float(__ushort_as_bfloat16(hb[2 * t]))) &&
                    e4m3_exact(__bfloat162float(__ushort_as_bfloat16(hb[2 * t + 1])));
        if (!okbf) okbfs = 0;
    }
    __syncthreads();
    const int mode = ok32s ? 0 : (okbfs ? 1 : 2);

    const size_t i = ((size_t)blockIdx.x * blockDim.x + threadIdx.x) * 16;
    uint4 o;
    if (mode == 0) {                       // float32 code values (expected)
        const float4* s = reinterpret_cast<const float4*>((const float*)qw + i);
        unsigned short h[8];
#pragma unroll
        for (int j = 0; j < 4; j++) {
            float4 v = s[j];
            float2 p0 = make_float2(v.x, v.y);
            float2 p1 = make_float2(v.z, v.w);
            h[2 * j + 0] = (unsigned short)__nv_cvt_float2_to_fp8x2(p0, __NV_SATFINITE, __NV_E4M3);
            h[2 * j + 1] = (unsigned short)__nv_cvt_float2_to_fp8x2(p1, __NV_SATFINITE, __NV_E4M3);
        }
        o.x = (uint32_t)h[0] | ((uint32_t)h[1] << 16);
        o.y = (uint32_t)h[2] | ((uint32_t)h[3] << 16);
        o.z = (uint32_t)h[4] | ((uint32_t)h[5] << 16);
        o.w = (uint32_t)h[6] | ((uint32_t)h[7] << 16);
    } else if (mode == 2) {                // raw e4m3 bytes
        o = *reinterpret_cast<const uint4*>((const uint8_t*)qw + i);
    } else {                               // bf16 codes
        const unsigned short* s = (const unsigned short*)qw + i;
        unsigned short h[8];
#pragma unroll
        for (int j = 0; j < 8; j++) {
            float2 p = make_float2(__bfloat162float(__ushort_as_bfloat16(s[2 * j])),
                                   __bfloat162float(__ushort_as_bfloat16(s[2 * j + 1])));
            h[j] = (unsigned short)__nv_cvt_float2_to_fp8x2(p, __NV_SATFINITE, __NV_E4M3);
        }
        o.x = (uint32_t)h[0] | ((uint32_t)h[1] << 16);
        o.y = (uint32_t)h[2] | ((uint32_t)h[3] << 16);
        o.z = (uint32_t)h[4] | ((uint32_t)h[5] << 16);
        o.w = (uint32_t)h[6] | ((uint32_t)h[7] << 16);
    }
    *reinterpret_cast<uint4*>(&g_B[i]) = o;
}

// ---------------------------------------------------------------------------
// Kernel 3: fp8 QMMA GEMM — exact R7 champion structure (392us, tensor 58%).
// BK=128, 3 stages, 2 CTAs/SM, fully unrolled chunk loop, transient fragments
// (ptxas-scheduled; explicit double-buffering spills — measured R8/R9).
// ---------------------------------------------------------------------------
__global__ void __launch_bounds__(256, 2) fp8lin_gemm(float* __restrict__ out,
                                                      const float* __restrict__ in_scale,
                                                      const float* __restrict__ w_scale,
                                                      const float* __restrict__ bias) {
    extern __shared__ char dsm[];
    const uint32_t smem0 = smem_u32(dsm);

    const int tid = threadIdx.x;
    const int wid = tid >> 5;
    const int lane = tid & 31;
    const int warp_m = wid >> 2;        // 0..1 -> 64 rows
    const int warp_n = wid & 3;         // 0..3 -> 32 cols

    const int n0 = blockIdx.x * BN;     // N fastest -> A-tile L2 reuse
    const int m0 = blockIdx.y * BM;

    // ---- hoisted loader addressing: 8 src pointers, 8 const dst offsets ----
    const int brow = tid >> 3;          // 0..31
    const int seg = (tid & 7) * 16;     // 0..112
    const uint8_t* sA[4];
    const uint8_t* sB[4];
    uint32_t dA[4], dB[4];
#pragma unroll
    for (int i = 0; i < 4; i++) {
        sA[i] = g_A + (size_t)(m0 + brow + 32 * i) * K_TOTAL + seg;
        sB[i] = g_B + (size_t)(n0 + brow + 32 * i) * K_TOTAL + seg;
        dA[i] = (uint32_t)((brow + 32 * i) * RS + seg);
        dB[i] = (uint32_t)(B_OFF + (brow + 32 * i) * RS + seg);
    }

#define ISSUE_STAGE(stage_base) do { \
        CP_ASYNC_16((stage_base) + dA[0], sA[0]); \
        CP_ASYNC_16((stage_base) + dA[1], sA[1]); \
        CP_ASYNC_16((stage_base) + dA[2], sA[2]); \
        CP_ASYNC_16((stage_base) + dA[3], sA[3]); \
        CP_ASYNC_16((stage_base) + dB[0], sB[0]); \
        CP_ASYNC_16((stage_base) + dB[1], sB[1]); \
        CP_ASYNC_16((stage_base) + dB[2], sB[2]); \
        CP_ASYNC_16((stage_base) + dB[3], sB[3]); \
        sA[0] += BK; sA[1] += BK; sA[2] += BK; sA[3] += BK; \
        sB[0] += BK; sB[1] += BK; sB[2] += BK; sB[3] += BK; \
        asm volatile("cp.async.commit_group;"); \
    } while (0)

    // ---- ldmatrix bases (validated R6/R7) ----
    const int amat = lane >> 3;
    const uint32_t a_base = smem0
        + (uint32_t)((warp_m * 64 + (amat & 1) * 8 + (lane & 7)) * RS + (amat >> 1) * 16);
    const uint32_t b_base = smem0 + (uint32_t)(B_OFF
        + (warp_n * 32 + ((lane >> 4) * 8) + (lane & 7)) * RS + ((lane >> 3) & 1) * 16);

    float acc[4][4][4];
#pragma unroll
    for (int mt = 0; mt < 4; mt++)
#pragma unroll
        for (int nt = 0; nt < 4; nt++)
#pragma unroll
            for (int q = 0; q < 4; q++) acc[mt][nt][q] = 0.0f;

    // Prefill stages 0,1 with chunks 0,1
    ISSUE_STAGE(smem0 + 0 * STAGE_BYTES);
    ISSUE_STAGE(smem0 + 1 * STAGE_BYTES);

#pragma unroll
    for (int c = 0; c < NUM_CHUNKS; c++) {
        if (c < NUM_CHUNKS - 1)
            asm volatile("cp.async.wait_group 1;");
        else
            asm volatile("cp.async.wait_group 0;");
        __syncthreads();

        if (c + 2 < NUM_CHUNKS)
            ISSUE_STAGE(smem0 + (uint32_t)(((c + 2) % STAGES) * STAGE_BYTES));

        const uint32_t soff = (uint32_t)((c % STAGES) * STAGE_BYTES);  // literal
#pragma unroll
        for (int ks = 0; ks < 4; ks++) {
            uint32_t a[4][4], b[4][2];
#pragma unroll
            for (int mt = 0; mt < 4; mt++)
                LDSM_X4(a[mt][0], a[mt][1], a[mt][2], a[mt][3],
                        a_base + soff + (uint32_t)(mt * 16 * RS + ks * 32));
#pragma unroll
            for (int p = 0; p < 2; p++)
                LDSM_X4(b[2 * p][0], b[2 * p][1], b[2 * p + 1][0], b[2 * p + 1][1],
                        b_base + soff + (uint32_t)(p * 16 * RS + ks * 32));
#pragma unroll
            for (int mt = 0; mt < 4; mt++)
#pragma unroll
                for (int nt = 0; nt < 4; nt++)
                    MMA_E4M3(acc[mt][nt], a[mt][0], a[mt][1], a[mt][2], a[mt][3],
                             b[nt][0], b[nt][1]);
        }
    }
#undef ISSUE_STAGE

    // ---------------- Epilogue: dequant scale + bias ----------------
    const float sc = __ldg(in_scale) * __ldg(w_scale);
    const int gid = lane >> 2;
    const int tig = lane & 3;

    float2 bv[4];
#pragma unroll
    for (int nt = 0; nt < 4; nt++)
        bv[nt] = *reinterpret_cast<const float2*>(bias + n0 + warp_n * 32 + nt * 8 + 2 * tig);

#pragma unroll
    for (int mt = 0; mt < 4; mt++) {
        const int row = m0 + warp_m * 64 + mt * 16 + gid;
#pragma unroll
        for (int nt = 0; nt < 4; nt++) {
            const int col = n0 + warp_n * 32 + nt * 8 + 2 * tig;
            float2 o0, o1;
            o0.x = acc[mt][nt][0] * sc + bv[nt].x;
            o0.y = acc[mt][nt][1] * sc + bv[nt].y;
            o1.x = acc[mt][nt][2] * sc + bv[nt].x;
            o1.y = acc[mt][nt][3] * sc + bv[nt].y;
            *reinterpret_cast<float2*>(out + (size_t)row * N_TOTAL + col) = o0;
            *reinterpret_cast<float2*>(out + (size_t)(row + 8) * N_TOTAL + col) = o1;
        }
    }
}

// ---------------------------------------------------------------------------
// Launch
// ---------------------------------------------------------------------------
extern "C" void kernel_launch(void* const* d_in, const int* in_sizes, int n_in,
                              void* d_out, int out_size) {
    const float* x = nullptr;
    const void* qweight = nullptr;
    const float* bias = nullptr;
    const float* s_first = nullptr;
    const float* s_second = nullptr;
    int x_idx = -1;

    for (int i = 0; i < n_in; i++) {
        long long sz = in_sizes[i];
        if (sz == (long long)M_TOTAL * K_TOTAL) { x = (const float*)d_in[i]; x_idx = i; }
        else if (sz == (long long)N_TOTAL * K_TOTAL) qweight = d_in[i];
        else if (sz == N_TOTAL) bias = (const float*)d_in[i];
        else if (sz == 1) { if (!s_first) s_first = (const float*)d_in[i];
                            else s_second = (const float*)d_in[i]; }
    }
    const float* wscale = (x_idx == 0) ? s_first : s_second;
    const float* iscale = (x_idx == 0) ? s_second : s_first;
    float* out = (float*)d_out;

    const size_t total = (size_t)M_TOTAL * K_TOTAL;
    fp8lin_quant<<<(unsigned)(total / (16 * 256)), 256>>>(x, iscale);
    fp8lin_wconv<<<(unsigned)((size_t)N_TOTAL * K_TOTAL / (16 * 256)), 256>>>(qweight);

    cudaFuncSetAttribute(fp8lin_gemm, cudaFuncAttributeMaxDynamicSharedMemorySize, SMEM_DYN);
    dim3 grid(N_TOTAL / BN, M_TOTAL / BM);
    fp8lin_gemm<<<grid, 256, SMEM_DYN>>>(out, iscale, wscale, bias);
}

// round 13
// speedup vs baseline: 1.6844x; 1.0104x over previous
#include <cuda_runtime.h>
#include <cuda_bf16.h>
#include <cuda_fp8.h>
#include <cstdint>
#include <math.h>

#define DEV __device__ __forceinline__

// ---------------------------------------------------------------------------
// Problem constants
// ---------------------------------------------------------------------------
static constexpr int M_TOTAL = 16384;   // B*S
static constexpr int N_TOTAL = 2048;    // OUT
static constexpr int K_TOTAL = 2048;    // IN

static constexpr int BM = 128;
static constexpr int BN = 128;
static constexpr int BK = 128;                   // fp8 bytes per K-chunk (full row)
static constexpr int NUM_CHUNKS = K_TOTAL / BK;  // 16
static constexpr int STAGES = 3;
static constexpr int RS = 144;                   // padded row stride (128 + 16)
static constexpr int B_OFF = BM * RS;            // 18432
static constexpr int STAGE_BYTES = (BM + BN) * RS;      // 36864
static constexpr int SMEM_DYN = STAGES * STAGE_BYTES;   // 110592 -> 2 CTAs/SM

// Fused prep kernel: first WCONV_BLOCKS blocks convert weights, rest quantize x
static constexpr int WCONV_BLOCKS = (N_TOTAL * K_TOTAL) / (16 * 256);   // 1024
static constexpr int QUANT_BLOCKS = (M_TOTAL * K_TOTAL) / (16 * 256);   // 8192

// ---------------------------------------------------------------------------
// Scratch
// ---------------------------------------------------------------------------
__device__ uint8_t g_A[(size_t)M_TOTAL * K_TOTAL];   // 32 MB
__device__ uint8_t g_B[(size_t)N_TOTAL * K_TOTAL];   // 4 MB

// ---------------------------------------------------------------------------
// PTX helpers
// ---------------------------------------------------------------------------
DEV uint32_t smem_u32(const void* p) {
    uint32_t a;
    asm("{ .reg .u64 t; cvta.to.shared.u64 t, %1; cvt.u32.u64 %0, t; }" : "=r"(a) : "l"(p));
    return a;
}

#define LDSM_X4(r0, r1, r2, r3, addr) \
    asm volatile("ldmatrix.sync.aligned.m8n8.x4.shared.b16 {%0,%1,%2,%3}, [%4];" \
                 : "=r"(r0), "=r"(r1), "=r"(r2), "=r"(r3) : "r"(addr))

// fp8 e4m3 MMA (validated R5-R10)
#define MMA_E4M3(c, a0, a1, a2, a3, b0, b1) \
    asm volatile("mma.sync.aligned.m16n8k32.row.col.f32.e4m3.e4m3.f32 " \
                 "{%0,%1,%2,%3}, {%4,%5,%6,%7}, {%8,%9}, {%0,%1,%2,%3};" \
                 : "+f"((c)[0]), "+f"((c)[1]), "+f"((c)[2]), "+f"((c)[3]) \
                 : "r"(a0), "r"(a1), "r"(a2), "r"(a3), "r"(b0), "r"(b1))

#define CP_ASYNC_16(dst, src) \
    asm volatile("cp.async.cg.shared.global [%0], [%1], 16;" :: "r"(dst), "l"(src))

DEV bool e4m3_exact(float v) {
    if (!isfinite(v) || fabsf(v) > 448.0f) return false;
    __nv_fp8_e4m3 e(v);
    return (float)e == v;
}

DEV uint4 pack8(const unsigned short* h) {
    uint4 o;
    o.x = (uint32_t)h[0] | ((uint32_t)h[1] << 16);
    o.y = (uint32_t)h[2] | ((uint32_t)h[3] << 16);
    o.z = (uint32_t)h[4] | ((uint32_t)h[5] << 16);
    o.w = (uint32_t)h[6] | ((uint32_t)h[7] << 16);
    return o;
}

// ---------------------------------------------------------------------------
// Kernel 1 (fused prep): blocks [0, WCONV_BLOCKS) -> weight conversion with
// per-block dtype probe; blocks [WCONV_BLOCKS, +QUANT_BLOCKS) -> x quantization.
// Probe: f32 must be tested before bf16 (valid f32 codes also pass bf16 test).
// ---------------------------------------------------------------------------
__global__ void __launch_bounds__(256) fp8lin_prep(const float* __restrict__ x,
                                                   const void* __restrict__ qw,
                                                   const float* __restrict__ in_scale) {
    const int t = threadIdx.x;

    if (blockIdx.x >= WCONV_BLOCKS) {
        // ---------------- quant path: x -> e4m3, 16 elems/thread ----------------
        const float r = 1.0f / __ldg(in_scale);
        const size_t i =
            ((size_t)(blockIdx.x - WCONV_BLOCKS) * blockDim.x + t) * 16;
        const float4* src = reinterpret_cast<const float4*>(x + i);

        float4 v0 = src[0], v1 = src[1], v2 = src[2], v3 = src[3];  // front-load (MLP)
        unsigned short h[8];
        {
            float2 p;
            p = make_float2(v0.x * r, v0.y * r);
            h[0] = (unsigned short)__nv_cvt_float2_to_fp8x2(p, __NV_SATFINITE, __NV_E4M3);
            p = make_float2(v0.z * r, v0.w * r);
            h[1] = (unsigned short)__nv_cvt_float2_to_fp8x2(p, __NV_SATFINITE, __NV_E4M3);
            p = make_float2(v1.x * r, v1.y * r);
            h[2] = (unsigned short)__nv_cvt_float2_to_fp8x2(p, __NV_SATFINITE, __NV_E4M3);
            p = make_float2(v1.z * r, v1.w * r);
            h[3] = (unsigned short)__nv_cvt_float2_to_fp8x2(p, __NV_SATFINITE, __NV_E4M3);
            p = make_float2(v2.x * r, v2.y * r);
            h[4] = (unsigned short)__nv_cvt_float2_to_fp8x2(p, __NV_SATFINITE, __NV_E4M3);
            p = make_float2(v2.z * r, v2.w * r);
            h[5] = (unsigned short)__nv_cvt_float2_to_fp8x2(p, __NV_SATFINITE, __NV_E4M3);
            p = make_float2(v3.x * r, v3.y * r);
            h[6] = (unsigned short)__nv_cvt_float2_to_fp8x2(p, __NV_SATFINITE, __NV_E4M3);
            p = make_float2(v3.z * r, v3.w * r);
            h[7] = (unsigned short)__nv_cvt_float2_to_fp8x2(p, __NV_SATFINITE, __NV_E4M3);
        }
        *reinterpret_cast<uint4*>(&g_A[i]) = pack8(h);
        return;
    }

    // ---------------- wconv path with folded dtype probe (R9/R10-validated) ----
    __shared__ int ok32s, okbfs;
    if (t == 0) { ok32s = 1; okbfs = 1; }
    __syncthreads();
    {
        const float* f = (const float*)qw;
        const unsigned short* hb = (const unsigned short*)qw;
        if (!e4m3_exact(f[t])) ok32s = 0;    // benign race: writers all store 0
        bool okbf = e4m3_exact(__bfloat162float(__ushort_as_bfloat16(hb[2 * t]))) &&
                    e4m3_exact(__bfloat162float(__ushort_as_bfloat16(hb[2 * t + 1])));
        if (!okbf) okbfs = 0;
    }
    __syncthreads();
    const int mode = ok32s ? 0 : (okbfs ? 1 : 2);

    const size_t i = ((size_t)blockIdx.x * blockDim.x + t) * 16;
    uint4 o;
    if (mode == 0) {                       // float32 code values (expected)
        const float4* s = reinterpret_cast<const float4*>((const float*)qw + i);
        unsigned short h[8];
#pragma unroll
        for (int j = 0; j < 4; j++) {
            float4 v = s[j];
            float2 p0 = make_float2(v.x, v.y);
            float2 p1 = make_float2(v.z, v.w);
            h[2 * j + 0] = (unsigned short)__nv_cvt_float2_to_fp8x2(p0, __NV_SATFINITE, __NV_E4M3);
            h[2 * j + 1] = (unsigned short)__nv_cvt_float2_to_fp8x2(p1, __NV_SATFINITE, __NV_E4M3);
        }
        o = pack8(h);
    } else if (mode == 2) {                // raw e4m3 bytes
        o = *reinterpret_cast<const uint4*>((const uint8_t*)qw + i);
    } else {                               // bf16 codes
        const unsigned short* s = (const unsigned short*)qw + i;
        unsigned short h[8];
#pragma unroll
        for (int j = 0; j < 8; j++) {
            float2 p = make_float2(__bfloat162float(__ushort_as_bfloat16(s[2 * j])),
                                   __bfloat162float(__ushort_as_bfloat16(s[2 * j + 1])));
            h[j] = (unsigned short)__nv_cvt_float2_to_fp8x2(p, __NV_SATFINITE, __NV_E4M3);
        }
        o = pack8(h);
    }
    *reinterpret_cast<uint4*>(&g_B[i]) = o;
}

// ---------------------------------------------------------------------------
// Kernel 2: fp8 QMMA GEMM — exact R7/R10 champion structure (392us, tensor 58%).
// BK=128, 3 stages, 2 CTAs/SM, fully unrolled chunk loop, transient fragments
// (ptxas-scheduled; explicit double-buffering spills — measured R8/R9). DO NOT
// add register pressure here.
// ---------------------------------------------------------------------------
__global__ void __launch_bounds__(256, 2) fp8lin_gemm(float* __restrict__ out,
                                                      const float* __restrict__ in_scale,
                                                      const float* __restrict__ w_scale,
                                                      const float* __restrict__ bias) {
    extern __shared__ char dsm[];
    const uint32_t smem0 = smem_u32(dsm);

    const int tid = threadIdx.x;
    const int wid = tid >> 5;
    const int lane = tid & 31;
    const int warp_m = wid >> 2;        // 0..1 -> 64 rows
    const int warp_n = wid & 3;         // 0..3 -> 32 cols

    const int n0 = blockIdx.x * BN;     // N fastest -> A-tile L2 reuse
    const int m0 = blockIdx.y * BM;

    // ---- hoisted loader addressing: 8 src pointers, 8 const dst offsets ----
    const int brow = tid >> 3;          // 0..31
    const int seg = (tid & 7) * 16;     // 0..112
    const uint8_t* sA[4];
    const uint8_t* sB[4];
    uint32_t dA[4], dB[4];
#pragma unroll
    for (int i = 0; i < 4; i++) {
        sA[i] = g_A + (size_t)(m0 + brow + 32 * i) * K_TOTAL + seg;
        sB[i] = g_B + (size_t)(n0 + brow + 32 * i) * K_TOTAL + seg;
        dA[i] = (uint32_t)((brow + 32 * i) * RS + seg);
        dB[i] = (uint32_t)(B_OFF + (brow + 32 * i) * RS + seg);
    }

#define ISSUE_STAGE(stage_base) do { \
        CP_ASYNC_16((stage_base) + dA[0], sA[0]); \
        CP_ASYNC_16((stage_base) + dA[1], sA[1]); \
        CP_ASYNC_16((stage_base) + dA[2], sA[2]); \
        CP_ASYNC_16((stage_base) + dA[3], sA[3]); \
        CP_ASYNC_16((stage_base) + dB[0], sB[0]); \
        CP_ASYNC_16((stage_base) + dB[1], sB[1]); \
        CP_ASYNC_16((stage_base) + dB[2], sB[2]); \
        CP_ASYNC_16((stage_base) + dB[3], sB[3]); \
        sA[0] += BK; sA[1] += BK; sA[2] += BK; sA[3] += BK; \
        sB[0] += BK; sB[1] += BK; sB[2] += BK; sB[3] += BK; \
        asm volatile("cp.async.commit_group;"); \
    } while (0)

    // ---- ldmatrix bases (validated R6/R7) ----
    const int amat = lane >> 3;
    const uint32_t a_base = smem0
        + (uint32_t)((warp_m * 64 + (amat & 1) * 8 + (lane & 7)) * RS + (amat >> 1) * 16);
    const uint32_t b_base = smem0 + (uint32_t)(B_OFF
        + (warp_n * 32 + ((lane >> 4) * 8) + (lane & 7)) * RS + ((lane >> 3) & 1) * 16);

    float acc[4][4][4];
#pragma unroll
    for (int mt = 0; mt < 4; mt++)
#pragma unroll
        for (int nt = 0; nt < 4; nt++)
#pragma unroll
            for (int q = 0; q < 4; q++) acc[mt][nt][q] = 0.0f;

    // Prefill stages 0,1 with chunks 0,1
    ISSUE_STAGE(smem0 + 0 * STAGE_BYTES);
    ISSUE_STAGE(smem0 + 1 * STAGE_BYTES);

#pragma unroll
    for (int c = 0; c < NUM_CHUNKS; c++) {
        if (c < NUM_CHUNKS - 1)
            asm volatile("cp.async.wait_group 1;");
        else
            asm volatile("cp.async.wait_group 0;");
        __syncthreads();

        if (c + 2 < NUM_CHUNKS)
            ISSUE_STAGE(smem0 + (uint32_t)(((c + 2) % STAGES) * STAGE_BYTES));

        const uint32_t soff = (uint32_t)((c % STAGES) * STAGE_BYTES);  // literal
#pragma unroll
        for (int ks = 0; ks < 4; ks++) {
            uint32_t a[4][4], b[4][2];
#pragma unroll
            for (int mt = 0; mt < 4; mt++)
                LDSM_X4(a[mt][0], a[mt][1], a[mt][2], a[mt][3],
                        a_base + soff + (uint32_t)(mt * 16 * RS + ks * 32));
#pragma unroll
            for (int p = 0; p < 2; p++)
                LDSM_X4(b[2 * p][0], b[2 * p][1], b[2 * p + 1][0], b[2 * p + 1][1],
                        b_base + soff + (uint32_t)(p * 16 * RS + ks * 32));
#pragma unroll
            for (int mt = 0; mt < 4; mt++)
#pragma unroll
                for (int nt = 0; nt < 4; nt++)
                    MMA_E4M3(acc[mt][nt], a[mt][0], a[mt][1], a[mt][2], a[mt][3],
                             b[nt][0], b[nt][1]);
        }
    }
#undef ISSUE_STAGE

    // ---------------- Epilogue: dequant scale + bias ----------------
    const float sc = __ldg(in_scale) * __ldg(w_scale);
    const int gid = lane >> 2;
    const int tig = lane & 3;

    float2 bv[4];
#pragma unroll
    for (int nt = 0; nt < 4; nt++)
        bv[nt] = *reinterpret_cast<const float2*>(bias + n0 + warp_n * 32 + nt * 8 + 2 * tig);

#pragma unroll
    for (int mt = 0; mt < 4; mt++) {
        const int row = m0 + warp_m * 64 + mt * 16 + gid;
#pragma unroll
        for (int nt = 0; nt < 4; nt++) {
            const int col = n0 + warp_n * 32 + nt * 8 + 2 * tig;
            float2 o0, o1;
            o0.x = acc[mt][nt][0] * sc + bv[nt].x;
            o0.y = acc[mt][nt][1] * sc + bv[nt].y;
            o1.x = acc[mt][nt][2] * sc + bv[nt].x;
            o1.y = acc[mt][nt][3] * sc + bv[nt].y;
            *reinterpret_cast<float2*>(out + (size_t)row * N_TOTAL + col) = o0;
            *reinterpret_cast<float2*>(out + (size_t)(row + 8) * N_TOTAL + col) = o1;
        }
    }
}

// ---------------------------------------------------------------------------
// Launch
// ---------------------------------------------------------------------------
extern "C" void kernel_launch(void* const* d_in, const int* in_sizes, int n_in,
                              void* d_out, int out_size) {
    const float* x = nullptr;
    const void* qweight = nullptr;
    const float* bias = nullptr;
    const float* s_first = nullptr;
    const float* s_second = nullptr;
    int x_idx = -1;

    for (int i = 0; i < n_in; i++) {
        long long sz = in_sizes[i];
        if (sz == (long long)M_TOTAL * K_TOTAL) { x = (const float*)d_in[i]; x_idx = i; }
        else if (sz == (long long)N_TOTAL * K_TOTAL) qweight = d_in[i];
        else if (sz == N_TOTAL) bias = (const float*)d_in[i];
        else if (sz == 1) { if (!s_first) s_first = (const float*)d_in[i];
                            else s_second = (const float*)d_in[i]; }
    }
    const float* wscale = (x_idx == 0) ? s_first : s_second;
    const float* iscale = (x_idx == 0) ? s_second : s_first;
    float* out = (float*)d_out;

    // Fused prep: weight conversion + activation quantization in one launch
    fp8lin_prep<<<WCONV_BLOCKS + QUANT_BLOCKS, 256>>>(x, qweight, iscale);

    cudaFuncSetAttribute(fp8lin_gemm, cudaFuncAttributeMaxDynamicSharedMemorySize, SMEM_DYN);
    dim3 grid(N_TOTAL / BN, M_TOTAL / BM);
    fp8lin_gemm<<<grid, 256, SMEM_DYN>>>(out, iscale, wscale, bias);
}

// round 15
// speedup vs baseline: 1.7704x; 1.0511x over previous
#include <cuda_runtime.h>
#include <cuda_bf16.h>
#include <cuda_fp8.h>
#include <cstdint>
#include <math.h>

#define DEV __device__ __forceinline__

// ---------------------------------------------------------------------------
// Problem constants
// ---------------------------------------------------------------------------
static constexpr int M_TOTAL = 16384;   // B*S
static constexpr int N_TOTAL = 2048;    // OUT
static constexpr int K_TOTAL = 2048;    // IN

static constexpr int BM = 128;
static constexpr int BN = 128;
static constexpr int BK = 128;                   // fp8 bytes per K-chunk (full row)
static constexpr int NUM_CHUNKS = K_TOTAL / BK;  // 16
static constexpr int STAGES = 3;
static constexpr int RS = 144;                   // padded row stride (128 + 16)
static constexpr int B_OFF = BM * RS;            // 18432
static constexpr int STAGE_BYTES = (BM + BN) * RS;      // 36864
static constexpr int SMEM_DYN = STAGES * STAGE_BYTES;   // 110592 -> 2 CTAs/SM

// Fused prep kernel: first WCONV_BLOCKS blocks convert weights, rest quantize x
static constexpr int WCONV_BLOCKS = (N_TOTAL * K_TOTAL) / (16 * 256);   // 1024
static constexpr int QUANT_BLOCKS = (M_TOTAL * K_TOTAL) / (16 * 256);   // 8192

// ---------------------------------------------------------------------------
// Scratch (36 MB total -> fits L2 if prep reads don't evict it)
// ---------------------------------------------------------------------------
__device__ uint8_t g_A[(size_t)M_TOTAL * K_TOTAL];   // 32 MB
__device__ uint8_t g_B[(size_t)N_TOTAL * K_TOTAL];   // 4 MB

// ---------------------------------------------------------------------------
// PTX helpers
// ---------------------------------------------------------------------------
DEV uint32_t smem_u32(const void* p) {
    uint32_t a;
    asm("{ .reg .u64 t; cvta.to.shared.u64 t, %1; cvt.u32.u64 %0, t; }" : "=r"(a) : "l"(p));
    return a;
}

#define LDSM_X4(r0, r1, r2, r3, addr) \
    asm volatile("ldmatrix.sync.aligned.m8n8.x4.shared.b16 {%0,%1,%2,%3}, [%4];" \
                 : "=r"(r0), "=r"(r1), "=r"(r2), "=r"(r3) : "r"(addr))

// fp8 e4m3 MMA (validated R5-R12)
#define MMA_E4M3(c, a0, a1, a2, a3, b0, b1) \
    asm volatile("mma.sync.aligned.m16n8k32.row.col.f32.e4m3.e4m3.f32 " \
                 "{%0,%1,%2,%3}, {%4,%5,%6,%7}, {%8,%9}, {%0,%1,%2,%3};" \
                 : "+f"((c)[0]), "+f"((c)[1]), "+f"((c)[2]), "+f"((c)[3]) \
                 : "r"(a0), "r"(a1), "r"(a2), "r"(a3), "r"(b0), "r"(b1))

#define CP_ASYNC_16(dst, src) \
    asm volatile("cp.async.cg.shared.global [%0], [%1], 16;" :: "r"(dst), "l"(src))

// Streaming (evict-first) 16B load: reads that must NOT pollute L2
DEV float4 ldcs4(const float4* p) {
    float4 v;
    asm volatile("ld.global.cs.v4.f32 {%0,%1,%2,%3}, [%4];"
                 : "=f"(v.x), "=f"(v.y), "=f"(v.z), "=f"(v.w) : "l"(p));
    return v;
}
DEV uint4 ldcs4u(const uint4* p) {
    uint4 v;
    asm volatile("ld.global.cs.v4.u32 {%0,%1,%2,%3}, [%4];"
                 : "=r"(v.x), "=r"(v.y), "=r"(v.z), "=r"(v.w) : "l"(p));
    return v;
}
// Streaming 8B store: write-once output, keep A/B slabs resident
DEV void stcs2(float2* p, float2 v) {
    asm volatile("st.global.cs.v2.f32 [%0], {%1,%2};" :: "l"(p), "f"(v.x), "f"(v.y));
}

DEV bool e4m3_exact(float v) {
    if (!isfinite(v) || fabsf(v) > 448.0f) return false;
    __nv_fp8_e4m3 e(v);
    return (float)e == v;
}

DEV uint4 pack8(const unsigned short* h) {
    uint4 o;
    o.x = (uint32_t)h[0] | ((uint32_t)h[1] << 16);
    o.y = (uint32_t)h[2] | ((uint32_t)h[3] << 16);
    o.z = (uint32_t)h[4] | ((uint32_t)h[5] << 16);
    o.w = (uint32_t)h[6] | ((uint32_t)h[7] << 16);
    return o;
}

// ---------------------------------------------------------------------------
// Kernel 1 (fused prep): blocks [0, WCONV_BLOCKS) -> weight conversion with
// per-block dtype probe; rest -> x quantization. All source reads use .cs
// (evict-first) so the freshly written g_A/g_B stay L2-resident for the GEMM.
// ---------------------------------------------------------------------------
__global__ void __launch_bounds__(256) fp8lin_prep(const float* __restrict__ x,
                                                   const void* __restrict__ qw,
                                                   const float* __restrict__ in_scale) {
    const int t = threadIdx.x;

    if (blockIdx.x >= WCONV_BLOCKS) {
        // ---------------- quant path: x -> e4m3, 16 elems/thread ----------------
        const float r = 1.0f / __ldg(in_scale);
        const size_t i =
            ((size_t)(blockIdx.x - WCONV_BLOCKS) * blockDim.x + t) * 16;
        const float4* src = reinterpret_cast<const float4*>(x + i);

        float4 v0 = ldcs4(src + 0), v1 = ldcs4(src + 1);   // front-load (MLP)
        float4 v2 = ldcs4(src + 2), v3 = ldcs4(src + 3);
        unsigned short h[8];
        {
            float2 p;
            p = make_float2(v0.x * r, v0.y * r);
            h[0] = (unsigned short)__nv_cvt_float2_to_fp8x2(p, __NV_SATFINITE, __NV_E4M3);
            p = make_float2(v0.z * r, v0.w * r);
            h[1] = (unsigned short)__nv_cvt_float2_to_fp8x2(p, __NV_SATFINITE, __NV_E4M3);
            p = make_float2(v1.x * r, v1.y * r);
            h[2] = (unsigned short)__nv_cvt_float2_to_fp8x2(p, __NV_SATFINITE, __NV_E4M3);
            p = make_float2(v1.z * r, v1.w * r);
            h[3] = (unsigned short)__nv_cvt_float2_to_fp8x2(p, __NV_SATFINITE, __NV_E4M3);
            p = make_float2(v2.x * r, v2.y * r);
            h[4] = (unsigned short)__nv_cvt_float2_to_fp8x2(p, __NV_SATFINITE, __NV_E4M3);
            p = make_float2(v2.z * r, v2.w * r);
            h[5] = (unsigned short)__nv_cvt_float2_to_fp8x2(p, __NV_SATFINITE, __NV_E4M3);
            p = make_float2(v3.x * r, v3.y * r);
            h[6] = (unsigned short)__nv_cvt_float2_to_fp8x2(p, __NV_SATFINITE, __NV_E4M3);
            p = make_float2(v3.z * r, v3.w * r);
            h[7] = (unsigned short)__nv_cvt_float2_to_fp8x2(p, __NV_SATFINITE, __NV_E4M3);
        }
        *reinterpret_cast<uint4*>(&g_A[i]) = pack8(h);
        return;
    }

    // ---------------- wconv path with folded dtype probe (R9-R12 validated) ----
    __shared__ int ok32s, okbfs;
    if (t == 0) { ok32s = 1; okbfs = 1; }
    __syncthreads();
    {
        const float* f = (const float*)qw;
        const unsigned short* hb = (const unsigned short*)qw;
        if (!e4m3_exact(f[t])) ok32s = 0;    // benign race: writers all store 0
        bool okbf = e4m3_exact(__bfloat162float(__ushort_as_bfloat16(hb[2 * t]))) &&
                    e4m3_exact(__bfloat162float(__ushort_as_bfloat16(hb[2 * t + 1])));
        if (!okbf) okbfs = 0;
    }
    __syncthreads();
    const int mode = ok32s ? 0 : (okbfs ? 1 : 2);

    const size_t i = ((size_t)blockIdx.x * blockDim.x + t) * 16;
    uint4 o;
    if (mode == 0) {                       // float32 code values (expected)
        const float4* s = reinterpret_cast<const float4*>((const float*)qw + i);
        unsigned short h[8];
#pragma unroll
        for (int j = 0; j < 4; j++) {
            float4 v = ldcs4(s + j);
            float2 p0 = make_float2(v.x, v.y);
            float2 p1 = make_float2(v.z, v.w);
            h[2 * j + 0] = (unsigned short)__nv_cvt_float2_to_fp8x2(p0, __NV_SATFINITE, __NV_E4M3);
            h[2 * j + 1] = (unsigned short)__nv_cvt_float2_to_fp8x2(p1, __NV_SATFINITE, __NV_E4M3);
        }
        o = pack8(h);
    } else if (mode == 2) {                // raw e4m3 bytes
        o = ldcs4u(reinterpret_cast<const uint4*>((const uint8_t*)qw + i));
    } else {                               // bf16 codes
        const unsigned short* s = (const unsigned short*)qw + i;
        unsigned short h[8];
#pragma unroll
        for (int j = 0; j < 8; j++) {
            float2 p = make_float2(__bfloat162float(__ushort_as_bfloat16(s[2 * j])),
                                   __bfloat162float(__ushort_as_bfloat16(s[2 * j + 1])));
            h[j] = (unsigned short)__nv_cvt_float2_to_fp8x2(p, __NV_SATFINITE, __NV_E4M3);
        }
        o = pack8(h);
    }
    *reinterpret_cast<uint4*>(&g_B[i]) = o;
}

// ---------------------------------------------------------------------------
// Kernel 2: fp8 QMMA GEMM — R7/R10 champion structure (391us, tensor 58%).
// Mainloop untouched (protected). Only change: epilogue stores use st.global.cs
// so the 128MB write-once output doesn't evict L2-resident A/B scratch.
// ---------------------------------------------------------------------------
__global__ void __launch_bounds__(256, 2) fp8lin_gemm(float* __restrict__ out,
                                                      const float* __restrict__ in_scale,
                                                      const float* __restrict__ w_scale,
                                                      const float* __restrict__ bias) {
    extern __shared__ char dsm[];
    const uint32_t smem0 = smem_u32(dsm);

    const int tid = threadIdx.x;
    const int wid = tid >> 5;
    const int lane = tid & 31;
    const int warp_m = wid >> 2;        // 0..1 -> 64 rows
    const int warp_n = wid & 3;         // 0..3 -> 32 cols

    const int n0 = blockIdx.x * BN;     // N fastest -> A-tile L2 reuse
    const int m0 = blockIdx.y * BM;

    // ---- hoisted loader addressing: 8 src pointers, 8 const dst offsets ----
    const int brow = tid >> 3;          // 0..31
    const int seg = (tid & 7) * 16;     // 0..112
    const uint8_t* sA[4];
    const uint8_t* sB[4];
    uint32_t dA[4], dB[4];
#pragma unroll
    for (int i = 0; i < 4; i++) {
        sA[i] = g_A + (size_t)(m0 + brow + 32 * i) * K_TOTAL + seg;
        sB[i] = g_B + (size_t)(n0 + brow + 32 * i) * K_TOTAL + seg;
        dA[i] = (uint32_t)((brow + 32 * i) * RS + seg);
        dB[i] = (uint32_t)(B_OFF + (brow + 32 * i) * RS + seg);
    }

#define ISSUE_STAGE(stage_base) do { \
        CP_ASYNC_16((stage_base) + dA[0], sA[0]); \
        CP_ASYNC_16((stage_base) + dA[1], sA[1]); \
        CP_ASYNC_16((stage_base) + dA[2], sA[2]); \
        CP_ASYNC_16((stage_base) + dA[3], sA[3]); \
        CP_ASYNC_16((stage_base) + dB[0], sB[0]); \
        CP_ASYNC_16((stage_base) + dB[1], sB[1]); \
        CP_ASYNC_16((stage_base) + dB[2], sB[2]); \
        CP_ASYNC_16((stage_base) + dB[3], sB[3]); \
        sA[0] += BK; sA[1] += BK; sA[2] += BK; sA[3] += BK; \
        sB[0] += BK; sB[1] += BK; sB[2] += BK; sB[3] += BK; \
        asm volatile("cp.async.commit_group;"); \
    } while (0)

    // ---- ldmatrix bases (validated R6/R7) ----
    const int amat = lane >> 3;
    const uint32_t a_base = smem0
        + (uint32_t)((warp_m * 64 + (amat & 1) * 8 + (lane & 7)) * RS + (amat >> 1) * 16);
    const uint32_t b_base = smem0 + (uint32_t)(B_OFF
        + (warp_n * 32 + ((lane >> 4) * 8) + (lane & 7)) * RS + ((lane >> 3) & 1) * 16);

    float acc[4][4][4];
#pragma unroll
    for (int mt = 0; mt < 4; mt++)
#pragma unroll
        for (int nt = 0; nt < 4; nt++)
#pragma unroll
            for (int q = 0; q < 4; q++) acc[mt][nt][q] = 0.0f;

    // Prefill stages 0,1 with chunks 0,1
    ISSUE_STAGE(smem0 + 0 * STAGE_BYTES);
    ISSUE_STAGE(smem0 + 1 * STAGE_BYTES);

#pragma unroll
    for (int c = 0; c < NUM_CHUNKS; c++) {
        if (c < NUM_CHUNKS - 1)
            asm volatile("cp.async.wait_group 1;");
        else
            asm volatile("cp.async.wait_group 0;");
        __syncthreads();

        if (c + 2 < NUM_CHUNKS)
            ISSUE_STAGE(smem0 + (uint32_t)(((c + 2) % STAGES) * STAGE_BYTES));

        const uint32_t soff = (uint32_t)((c % STAGES) * STAGE_BYTES);  // literal
#pragma unroll
        for (int ks = 0; ks < 4; ks++) {
            uint32_t a[4][4], b[4][2];
#pragma unroll
            for (int mt = 0; mt < 4; mt++)
                LDSM_X4(a[mt][0], a[mt][1], a[mt][2], a[mt][3],
                        a_base + soff + (uint32_t)(mt * 16 * RS + ks * 32));
#pragma unroll
            for (int p = 0; p < 2; p++)
                LDSM_X4(b[2 * p][0], b[2 * p][1], b[2 * p + 1][0], b[2 * p + 1][1],
                        b_base + soff + (uint32_t)(p * 16 * RS + ks * 32));
#pragma unroll
            for (int mt = 0; mt < 4; mt++)
#pragma unroll
                for (int nt = 0; nt < 4; nt++)
                    MMA_E4M3(acc[mt][nt], a[mt][0], a[mt][1], a[mt][2], a[mt][3],
                             b[nt][0], b[nt][1]);
        }
    }
#undef ISSUE_STAGE

    // ---------------- Epilogue: dequant scale + bias, streaming stores -------
    const float sc = __ldg(in_scale) * __ldg(w_scale);
    const int gid = lane >> 2;
    const int tig = lane & 3;

    float2 bv[4];
#pragma unroll
    for (int nt = 0; nt < 4; nt++)
        bv[nt] = *reinterpret_cast<const float2*>(bias + n0 + warp_n * 32 + nt * 8 + 2 * tig);

#pragma unroll
    for (int mt = 0; mt < 4; mt++) {
        const int row = m0 + warp_m * 64 + mt * 16 + gid;
#pragma unroll
        for (int nt = 0; nt < 4; nt++) {
            const int col = n0 + warp_n * 32 + nt * 8 + 2 * tig;
            float2 o0, o1;
            o0.x = acc[mt][nt][0] * sc + bv[nt].x;
            o0.y = acc[mt][nt][1] * sc + bv[nt].y;
            o1.x = acc[mt][nt][2] * sc + bv[nt].x;
            o1.y = acc[mt][nt][3] * sc + bv[nt].y;
            stcs2(reinterpret_cast<float2*>(out + (size_t)row * N_TOTAL + col), o0);
            stcs2(reinterpret_cast<float2*>(out + (size_t)(row + 8) * N_TOTAL + col), o1);
        }
    }
}

// ---------------------------------------------------------------------------
// Launch
// ---------------------------------------------------------------------------
extern "C" void kernel_launch(void* const* d_in, const int* in_sizes, int n_in,
                              void* d_out, int out_size) {
    const float* x = nullptr;
    const void* qweight = nullptr;
    const float* bias = nullptr;
    const float* s_first = nullptr;
    const float* s_second = nullptr;
    int x_idx = -1;

    for (int i = 0; i < n_in; i++) {
        long long sz = in_sizes[i];
        if (sz == (long long)M_TOTAL * K_TOTAL) { x = (const float*)d_in[i]; x_idx = i; }
        else if (sz == (long long)N_TOTAL * K_TOTAL) qweight = d_in[i];
        else if (sz == N_TOTAL) bias = (const float*)d_in[i];
        else if (sz == 1) { if (!s_first) s_first = (const float*)d_in[i];
                            else s_second = (const float*)d_in[i]; }
    }
    const float* wscale = (x_idx == 0) ? s_first : s_second;
    const float* iscale = (x_idx == 0) ? s_second : s_first;
    float* out = (float*)d_out;

    // Fused prep: weight conversion + activation quantization in one launch
    fp8lin_prep<<<WCONV_BLOCKS + QUANT_BLOCKS, 256>>>(x, qweight, iscale);

    cudaFuncSetAttribute(fp8lin_gemm, cudaFuncAttributeMaxDynamicSharedMemorySize, SMEM_DYN);
    dim3 grid(N_TOTAL / BN, M_TOTAL / BM);
    fp8lin_gemm<<<grid, 256, SMEM_DYN>>>(out, iscale, wscale, bias);
}